// round 1
// baseline (speedup 1.0000x reference)
#include <cuda_runtime.h>
#include <cstdint>

// CapsuleCONV routing, fused single pass.
// input : (32, 32, 32, 32, 16)  f32
// ncv   : (32, 32, 15, 15, 16)  f32
// w     : (3, 3, 32, 4, 4, 32)  f32
// gamma : (16,), beta : (16,)
// out   : (32, 32, 15, 15, 16)  f32
//
// CTA = (b, h). 480 threads: warp = w-position (0..14), lane = m (0..31).
// smem: full unfolded input row slice [n][k][col 0..30][c] + double-buffered w chunk.

#define HOUT 15
#define WOUT 15

#define S_INP_FLOATS (32 * 3 * 496)   // 31 cols * 16 ch = 496 per (n,k)
#define S_W_FLOATS   (2 * 512)
#define SMEM_BYTES   ((S_INP_FLOATS + S_W_FLOATS) * 4)

static __device__ __forceinline__ void cpasync16(uint32_t dst, const void* src) {
    asm volatile("cp.async.cg.shared.global [%0], [%1], 16;" :: "r"(dst), "l"(src));
}

__global__ __launch_bounds__(480, 1)
void capsule_kernel(const float* __restrict__ input,
                    const float* __restrict__ ncv,
                    const float* __restrict__ wgt,
                    const float* __restrict__ gamma,
                    const float* __restrict__ beta,
                    float* __restrict__ out)
{
    extern __shared__ float smem[];
    float* s_inp = smem;                    // [n][k][496]
    float* s_w   = smem + S_INP_FLOATS;     // [2][512] : [x*4+dd][m]

    const int h    = blockIdx.x;
    const int b    = blockIdx.y;
    const int tid  = threadIdx.x;
    const int wpos = tid >> 5;    // 0..14
    const int lane = tid & 31;    // m

    // ---- Load input slice: rows y = 2h+k, cols 0..30, all n. Coalesced float4. ----
    {
        const float4* gin = reinterpret_cast<const float4*>(input);
        float4* s4 = reinterpret_cast<float4*>(s_inp);
        #pragma unroll 1
        for (int i = tid; i < 32 * 3 * 124; i += 480) {
            int nk = i / 124;
            int v  = i - nk * 124;
            int n  = nk / 3;
            int k  = nk - n * 3;
            // global row (b, n, 2h+k): 32 cols * 16 ch = 128 float4 per row; take first 124.
            s4[nk * 124 + v] = gin[(((b * 32 + n) * 32) + (2 * h + k)) * 128 + v];
        }
    }

    // ---- ncv for this (b, m=lane, h, w=wpos): 16 regs. channel = a*4 + d ----
    float ncvreg[16];
    {
        const float4* g = reinterpret_cast<const float4*>(
            ncv + ((((size_t)b * 32 + lane) * HOUT + h) * WOUT + wpos) * 16);
        float4 t;
        t = g[0]; ncvreg[0]  = t.x; ncvreg[1]  = t.y; ncvreg[2]  = t.z; ncvreg[3]  = t.w;
        t = g[1]; ncvreg[4]  = t.x; ncvreg[5]  = t.y; ncvreg[6]  = t.z; ncvreg[7]  = t.w;
        t = g[2]; ncvreg[8]  = t.x; ncvreg[9]  = t.y; ncvreg[10] = t.z; ncvreg[11] = t.w;
        t = g[3]; ncvreg[12] = t.x; ncvreg[13] = t.y; ncvreg[14] = t.z; ncvreg[15] = t.w;
    }

    float acc[16];
    #pragma unroll
    for (int j = 0; j < 16; ++j) acc[j] = 0.f;

    const uint32_t swb = (uint32_t)__cvta_generic_to_shared(s_w);

    // Preload w chunk for (kl=0, n=0). Chunk = (kl*32 + n)*512 floats, contiguous.
    if (tid < 128) cpasync16(swb + tid * 16u, (const float4*)wgt + tid);
    asm volatile("cp.async.commit_group;");
    asm volatile("cp.async.wait_group 0;" ::: "memory");
    __syncthreads();

    int buf = 0;
    #pragma unroll 1
    for (int n = 0; n < 32; ++n) {
        int k = 0, l = 0;
        #pragma unroll 1
        for (int kl = 0; kl < 9; ++kl) {
            // ---- prefetch next w chunk into the other buffer (overlapped) ----
            {
                int n2 = n, kl2 = kl + 1;
                if (kl2 == 9) { kl2 = 0; n2 = n + 1; }
                if (n2 < 32 && tid < 128) {
                    const float4* src =
                        (const float4*)(wgt + (size_t)(kl2 * 32 + n2) * 512) + tid;
                    cpasync16(swb + (uint32_t)((buf ^ 1) * 2048) + tid * 16u, src);
                }
                asm volatile("cp.async.commit_group;");
            }

            const float* wb = s_w + buf * 512;

            // iv[a*4+x] = input[b, n, 2h+k, 2w+l, a*4+x]  (warp-broadcast LDS.128)
            float iv[16];
            {
                const float4* ivp = reinterpret_cast<const float4*>(
                    s_inp + (n * 3 + k) * 496 + (2 * wpos + l) * 16);
                float4 t;
                t = ivp[0]; iv[0]  = t.x; iv[1]  = t.y; iv[2]  = t.z; iv[3]  = t.w;
                t = ivp[1]; iv[4]  = t.x; iv[5]  = t.y; iv[6]  = t.z; iv[7]  = t.w;
                t = ivp[2]; iv[8]  = t.x; iv[9]  = t.y; iv[10] = t.z; iv[11] = t.w;
                t = ivp[3]; iv[12] = t.x; iv[13] = t.y; iv[14] = t.z; iv[15] = t.w;
            }

            // wr[x*4+dd] = w[k,l,n,x,dd,m=lane]   (bank = lane: conflict-free)
            float wr[16];
            #pragma unroll
            for (int j = 0; j < 16; ++j) wr[j] = wb[j * 32 + lane];

            // V[a*4+dd] = sum_x iv[a,x] * wr[x,dd]
            float V[16];
            #pragma unroll
            for (int a = 0; a < 4; ++a) {
                #pragma unroll
                for (int dd = 0; dd < 4; ++dd) {
                    float v = iv[a * 4 + 0] * wr[0 + dd];
                    v = fmaf(iv[a * 4 + 1], wr[4  + dd], v);
                    v = fmaf(iv[a * 4 + 2], wr[8  + dd], v);
                    v = fmaf(iv[a * 4 + 3], wr[12 + dd], v);
                    V[a * 4 + dd] = v;
                }
            }

            // qk = scale * sum_{a,dd} V * ncv
            float q = V[0] * ncvreg[0];
            #pragma unroll
            for (int j = 1; j < 16; ++j) q = fmaf(V[j], ncvreg[j], q);
            q *= 0.25f;

            // softmax over m (= lanes of this warp)
            float mx = q;
            #pragma unroll
            for (int o = 16; o > 0; o >>= 1)
                mx = fmaxf(mx, __shfl_xor_sync(0xffffffffu, mx, o));
            float e = __expf(q - mx);
            float s = e;
            #pragma unroll
            for (int o = 16; o > 0; o >>= 1)
                s += __shfl_xor_sync(0xffffffffu, s, o);
            float p = __fdividef(e, s);
            // reference's extra /(sum+1e-10): sum==1 and 1+1e-10 rounds to 1 in f32 -> no-op

            #pragma unroll
            for (int j = 0; j < 16; ++j) acc[j] = fmaf(p, V[j], acc[j]);

            asm volatile("cp.async.wait_group 0;" ::: "memory");
            __syncthreads();
            buf ^= 1;

            if (++l == 3) { l = 0; ++k; }
        }
    }

    // ---- LayerNorm over the 16 output channels ----
    float mu = 0.f;
    #pragma unroll
    for (int j = 0; j < 16; ++j) mu += acc[j];
    mu *= (1.f / 16.f);
    float var = 0.f;
    #pragma unroll
    for (int j = 0; j < 16; ++j) { float d = acc[j] - mu; var = fmaf(d, d, var); }
    var *= (1.f / 16.f);
    const float inv = rsqrtf(var + 1e-5f);

    float o[16];
    #pragma unroll
    for (int j = 0; j < 16; ++j)
        o[j] = fmaf((acc[j] - mu) * inv, __ldg(gamma + j), __ldg(beta + j));

    float4* gout = reinterpret_cast<float4*>(
        out + ((((size_t)b * 32 + lane) * HOUT + h) * WOUT + wpos) * 16);
    gout[0] = make_float4(o[0],  o[1],  o[2],  o[3]);
    gout[1] = make_float4(o[4],  o[5],  o[6],  o[7]);
    gout[2] = make_float4(o[8],  o[9],  o[10], o[11]);
    gout[3] = make_float4(o[12], o[13], o[14], o[15]);
}

extern "C" void kernel_launch(void* const* d_in, const int* in_sizes, int n_in,
                              void* d_out, int out_size)
{
    const float* input = (const float*)d_in[0];
    const float* ncv   = (const float*)d_in[1];
    const float* wgt   = (const float*)d_in[2];
    const float* gamma = (const float*)d_in[3];
    const float* beta  = (const float*)d_in[4];
    // d_in[5] = num_iter (unused by the reference computation; always 1)
    float* out = (float*)d_out;

    cudaFuncSetAttribute(capsule_kernel,
                         cudaFuncAttributeMaxDynamicSharedMemorySize, SMEM_BYTES);
    dim3 grid(HOUT, 32);
    capsule_kernel<<<grid, 480, SMEM_BYTES>>>(input, ncv, wgt, gamma, beta, out);
}

// round 2
// speedup vs baseline: 1.2833x; 1.2833x over previous
#include <cuda_runtime.h>
#include <cstdint>

// CapsuleCONV routing — R2: n-split (2 CTAs/SM) + ILP2 (2 wpos/thread).
// Main kernel accumulates pre-LN partial sums per n-half into g_part;
// reduce kernel sums halves + LayerNorm.

#define HOUT 15
#define WOUT 15
#define NHALF 16
#define NSITES (32 * 32 * HOUT * WOUT)   // 230400 (b,m,h,w)

__device__ float g_part[2u * NSITES * 16];   // [half][site][16]

#define S_INP_FLOATS (NHALF * 3 * 31 * 16)   // 23808 floats = 93 KB
#define S_W_FLOATS   (2 * 512)               // double-buffered w chunk
#define SMEM_BYTES   ((S_INP_FLOATS + S_W_FLOATS) * 4)

static __device__ __forceinline__ void cpasync16(uint32_t dst, const void* src) {
    asm volatile("cp.async.cg.shared.global [%0], [%1], 16;" :: "r"(dst), "l"(src));
}

static __device__ __forceinline__ void ld16(float* r, const float* p) {
    const float4* g = reinterpret_cast<const float4*>(p);
    float4 t;
    t = g[0]; r[0]  = t.x; r[1]  = t.y; r[2]  = t.z; r[3]  = t.w;
    t = g[1]; r[4]  = t.x; r[5]  = t.y; r[6]  = t.z; r[7]  = t.w;
    t = g[2]; r[8]  = t.x; r[9]  = t.y; r[10] = t.z; r[11] = t.w;
    t = g[3]; r[12] = t.x; r[13] = t.y; r[14] = t.z; r[15] = t.w;
}

// One (wpos) work unit for one (n,kl) step: votes, qk, softmax over m, accumulate.
static __device__ __forceinline__ void compute_unit(
    const float* __restrict__ ivp,     // smem ptr to 16 input channels (broadcast)
    const float* __restrict__ wr,      // 16 w values for m=lane (regs)
    const float* __restrict__ ncvr,    // 16 ncv values (regs)
    float* __restrict__ acc)           // 16 accumulators (regs)
{
    float iv[16];
    ld16(iv, ivp);

    float V[16];
    #pragma unroll
    for (int a = 0; a < 4; ++a) {
        #pragma unroll
        for (int dd = 0; dd < 4; ++dd) {
            float v = iv[a * 4 + 0] * wr[0 + dd];
            v = fmaf(iv[a * 4 + 1], wr[4  + dd], v);
            v = fmaf(iv[a * 4 + 2], wr[8  + dd], v);
            v = fmaf(iv[a * 4 + 3], wr[12 + dd], v);
            V[a * 4 + dd] = v;
        }
    }

    float q = V[0] * ncvr[0];
    #pragma unroll
    for (int j = 1; j < 16; ++j) q = fmaf(V[j], ncvr[j], q);
    q *= 0.25f;

    float mx = q;
    #pragma unroll
    for (int o = 16; o > 0; o >>= 1)
        mx = fmaxf(mx, __shfl_xor_sync(0xffffffffu, mx, o));
    float e = __expf(q - mx);
    float s = e;
    #pragma unroll
    for (int o = 16; o > 0; o >>= 1)
        s += __shfl_xor_sync(0xffffffffu, s, o);
    float p = __fdividef(e, s);
    // reference's extra /(sum+1e-10) is a no-op in f32 (sum==1)

    #pragma unroll
    for (int j = 0; j < 16; ++j) acc[j] = fmaf(p, V[j], acc[j]);
}

__global__ __launch_bounds__(256, 2)
void capsule_main(const float* __restrict__ input,
                  const float* __restrict__ ncv,
                  const float* __restrict__ wgt)
{
    extern __shared__ float smem[];
    float* s_inp = smem;                    // [16 n][3 k][31 col][16 ch]
    float* s_w   = smem + S_INP_FLOATS;     // [2][512] : [x*4+dd][m]

    const int h    = blockIdx.x;
    const int b    = blockIdx.y;
    const int nh   = blockIdx.z;            // n half: 0 or 1
    const int tid  = threadIdx.x;
    const int warp = tid >> 5;
    const int lane = tid & 31;               // m
    const int w0   = 2 * warp;
    const int w1   = 2 * warp + 1;
    const bool u1ok = (w1 < WOUT);           // warp 7 handles only wpos 14
    const int n0   = nh * NHALF;

    // ---- input slice for this (b,h,nhalf): rows 2h+k, cols 0..30, n0..n0+15 ----
    {
        const float4* gin = reinterpret_cast<const float4*>(input);
        float4* s4 = reinterpret_cast<float4*>(s_inp);
        #pragma unroll 1
        for (int i = tid; i < NHALF * 3 * 124; i += 256) {
            int nk = i / 124;
            int v  = i - nk * 124;
            int n  = nk / 3;
            int k  = nk - n * 3;
            s4[nk * 124 + v] = gin[(((b * 32 + n0 + n) * 32) + (2 * h + k)) * 128 + v];
        }
    }

    // ---- ncv for (b, m=lane, h, w0/w1) ----
    float ncv0[16], ncv1[16];
    ld16(ncv0, ncv + ((((size_t)b * 32 + lane) * HOUT + h) * WOUT + w0) * 16);
    if (u1ok)
        ld16(ncv1, ncv + ((((size_t)b * 32 + lane) * HOUT + h) * WOUT + w1) * 16);
    else {
        #pragma unroll
        for (int j = 0; j < 16; ++j) ncv1[j] = 0.f;
    }

    float acc0[16], acc1[16];
    #pragma unroll
    for (int j = 0; j < 16; ++j) { acc0[j] = 0.f; acc1[j] = 0.f; }

    const uint32_t swb = (uint32_t)__cvta_generic_to_shared(s_w);

    // preload w chunk (kl=0, n=n0); chunk c = kl*32+n, 512 floats contiguous
    if (tid < 128)
        cpasync16(swb + tid * 16u, (const float4*)(wgt + (size_t)n0 * 512) + tid);
    asm volatile("cp.async.commit_group;");
    asm volatile("cp.async.wait_group 0;" ::: "memory");
    __syncthreads();

    int buf = 0;
    #pragma unroll 1
    for (int ni = 0; ni < NHALF; ++ni) {
        int k = 0, l = 0;
        #pragma unroll 1
        for (int kl = 0; kl < 9; ++kl) {
            // prefetch next chunk
            {
                int ni2 = ni, kl2 = kl + 1;
                if (kl2 == 9) { kl2 = 0; ++ni2; }
                if (ni2 < NHALF && tid < 128) {
                    const float4* src =
                        (const float4*)(wgt + (size_t)(kl2 * 32 + n0 + ni2) * 512) + tid;
                    cpasync16(swb + (uint32_t)((buf ^ 1) * 2048) + tid * 16u, src);
                }
                asm volatile("cp.async.commit_group;");
            }

            const float* wb = s_w + buf * 512;
            float wr[16];
            #pragma unroll
            for (int j = 0; j < 16; ++j) wr[j] = wb[j * 32 + lane];

            const float* rowbase = s_inp + (ni * 3 + k) * 496 + l * 16;
            compute_unit(rowbase + (2 * w0) * 16, wr, ncv0, acc0);
            if (u1ok)
                compute_unit(rowbase + (2 * w1) * 16, wr, ncv1, acc1);

            asm volatile("cp.async.wait_group 0;" ::: "memory");
            __syncthreads();
            buf ^= 1;

            if (++l == 3) { l = 0; ++k; }
        }
    }

    // ---- store raw partial sums (pre-LN) ----
    {
        size_t site0 = (((size_t)b * 32 + lane) * HOUT + h) * WOUT + w0;
        float4* g0 = reinterpret_cast<float4*>(g_part + ((size_t)nh * NSITES + site0) * 16);
        g0[0] = make_float4(acc0[0],  acc0[1],  acc0[2],  acc0[3]);
        g0[1] = make_float4(acc0[4],  acc0[5],  acc0[6],  acc0[7]);
        g0[2] = make_float4(acc0[8],  acc0[9],  acc0[10], acc0[11]);
        g0[3] = make_float4(acc0[12], acc0[13], acc0[14], acc0[15]);
        if (u1ok) {
            size_t site1 = site0 + 1;
            float4* g1 = reinterpret_cast<float4*>(g_part + ((size_t)nh * NSITES + site1) * 16);
            g1[0] = make_float4(acc1[0],  acc1[1],  acc1[2],  acc1[3]);
            g1[1] = make_float4(acc1[4],  acc1[5],  acc1[6],  acc1[7]);
            g1[2] = make_float4(acc1[8],  acc1[9],  acc1[10], acc1[11]);
            g1[3] = make_float4(acc1[12], acc1[13], acc1[14], acc1[15]);
        }
    }
}

__global__ __launch_bounds__(256)
void reduce_ln(float* __restrict__ out,
               const float* __restrict__ gamma,
               const float* __restrict__ beta)
{
    int s = blockIdx.x * 256 + threadIdx.x;
    if (s >= NSITES) return;

    const float4* p0 = reinterpret_cast<const float4*>(g_part) + (size_t)s * 4;
    const float4* p1 = reinterpret_cast<const float4*>(g_part) + ((size_t)NSITES + s) * 4;

    float v[16];
    #pragma unroll
    for (int i = 0; i < 4; ++i) {
        float4 a = p0[i], c = p1[i];
        v[i * 4 + 0] = a.x + c.x;
        v[i * 4 + 1] = a.y + c.y;
        v[i * 4 + 2] = a.z + c.z;
        v[i * 4 + 3] = a.w + c.w;
    }

    float mu = 0.f;
    #pragma unroll
    for (int j = 0; j < 16; ++j) mu += v[j];
    mu *= (1.f / 16.f);
    float var = 0.f;
    #pragma unroll
    for (int j = 0; j < 16; ++j) { float d = v[j] - mu; var = fmaf(d, d, var); }
    var *= (1.f / 16.f);
    const float inv = rsqrtf(var + 1e-5f);

    float o[16];
    #pragma unroll
    for (int j = 0; j < 16; ++j)
        o[j] = fmaf((v[j] - mu) * inv, __ldg(gamma + j), __ldg(beta + j));

    float4* gout = reinterpret_cast<float4*>(out + (size_t)s * 16);
    gout[0] = make_float4(o[0],  o[1],  o[2],  o[3]);
    gout[1] = make_float4(o[4],  o[5],  o[6],  o[7]);
    gout[2] = make_float4(o[8],  o[9],  o[10], o[11]);
    gout[3] = make_float4(o[12], o[13], o[14], o[15]);
}

extern "C" void kernel_launch(void* const* d_in, const int* in_sizes, int n_in,
                              void* d_out, int out_size)
{
    const float* input = (const float*)d_in[0];
    const float* ncv   = (const float*)d_in[1];
    const float* wgt   = (const float*)d_in[2];
    const float* gamma = (const float*)d_in[3];
    const float* beta  = (const float*)d_in[4];
    float* out = (float*)d_out;

    cudaFuncSetAttribute(capsule_main,
                         cudaFuncAttributeMaxDynamicSharedMemorySize, SMEM_BYTES);
    dim3 grid(HOUT, 32, 2);
    capsule_main<<<grid, 256, SMEM_BYTES>>>(input, ncv, wgt);
    reduce_ln<<<(NSITES + 255) / 256, 256>>>(out, gamma, beta);
}

// round 3
// speedup vs baseline: 1.5731x; 1.2258x over previous
#include <cuda_runtime.h>
#include <cstdint>

// CapsuleCONV routing — R3: packed f32x2 FFMA2 mainloop + 3-chunk w batching.
// Grid: (HOUT, B, 2 n-halves). 256 thr: warp = 2 w-positions, lane = m.

#define HOUT 15
#define WOUT 15
#define NHALF 16
#define NSITES (32 * 32 * HOUT * WOUT)   // 230400 (b,m,h,w)

__device__ float g_part[2u * NSITES * 16];   // [half][site][16]

#define S_INP_FLOATS (NHALF * 3 * 31 * 16)   // 23808 floats = 93 KB
#define S_W_FLOATS   (2 * 3 * 512)           // double-buffered 3-chunk w group
#define SMEM_BYTES   ((S_INP_FLOATS + S_W_FLOATS) * 4)

typedef unsigned long long u64;

static __device__ __forceinline__ void cpasync16(uint32_t dst, const void* src) {
    asm volatile("cp.async.cg.shared.global [%0], [%1], 16;" :: "r"(dst), "l"(src));
}
static __device__ __forceinline__ u64 pack2(float lo, float hi) {
    u64 r; asm("mov.b64 %0, {%1, %2};" : "=l"(r) : "f"(lo), "f"(hi)); return r;
}
static __device__ __forceinline__ u64 dup2(float v) { return pack2(v, v); }
static __device__ __forceinline__ void unpack2(u64 v, float& lo, float& hi) {
    asm("mov.b64 {%0, %1}, %2;" : "=f"(lo), "=f"(hi) : "l"(v));
}
static __device__ __forceinline__ u64 fma2(u64 a, u64 b, u64 c) {
    u64 d; asm("fma.rn.f32x2 %0, %1, %2, %3;" : "=l"(d) : "l"(a), "l"(b), "l"(c)); return d;
}
static __device__ __forceinline__ u64 mul2(u64 a, u64 b) {
    u64 d; asm("mul.rn.f32x2 %0, %1, %2;" : "=l"(d) : "l"(a), "l"(b)); return d;
}
static __device__ __forceinline__ void ld16(float* r, const float* p) {
    const float4* g = reinterpret_cast<const float4*>(p);
    float4 t;
    t = g[0]; r[0]  = t.x; r[1]  = t.y; r[2]  = t.z; r[3]  = t.w;
    t = g[1]; r[4]  = t.x; r[5]  = t.y; r[6]  = t.z; r[7]  = t.w;
    t = g[2]; r[8]  = t.x; r[9]  = t.y; r[10] = t.z; r[11] = t.w;
    t = g[3]; r[12] = t.x; r[13] = t.y; r[14] = t.z; r[15] = t.w;
}

// One (wpos) unit: votes (packed), qk, softmax over m, packed accumulate.
static __device__ __forceinline__ void compute_unit(
    const float* __restrict__ ivp,   // smem: 16 input channels (warp broadcast)
    const u64*  __restrict__ wr2,    // 8 packed w pairs for m=lane
    const u64*  __restrict__ ncv2,   // 8 packed ncv pairs
    u64*        __restrict__ acc2)   // 8 packed accumulators
{
    float iv[16];
    ld16(iv, ivp);
    u64 ivd[16];
    #pragma unroll
    for (int j = 0; j < 16; ++j) ivd[j] = dup2(iv[j]);

    // V2[a*2+p] = sum_x iv[a,x] (x) wr2[x*2+p]   (channels a*4+2p, a*4+2p+1)
    u64 V2[8];
    #pragma unroll
    for (int a = 0; a < 4; ++a) {
        #pragma unroll
        for (int p = 0; p < 2; ++p) {
            u64 v = mul2(ivd[a * 4 + 0], wr2[0 * 2 + p]);
            v = fma2(ivd[a * 4 + 1], wr2[1 * 2 + p], v);
            v = fma2(ivd[a * 4 + 2], wr2[2 * 2 + p], v);
            v = fma2(ivd[a * 4 + 3], wr2[3 * 2 + p], v);
            V2[a * 2 + p] = v;
        }
    }

    // qk = 0.25 * sum_j V . ncv
    u64 qk2 = mul2(V2[0], ncv2[0]);
    #pragma unroll
    for (int j = 1; j < 8; ++j) qk2 = fma2(V2[j], ncv2[j], qk2);
    float qlo, qhi;
    unpack2(qk2, qlo, qhi);
    float q = (qlo + qhi) * 0.25f;

    // softmax over m (lanes)
    float mx = q;
    #pragma unroll
    for (int o = 16; o > 0; o >>= 1)
        mx = fmaxf(mx, __shfl_xor_sync(0xffffffffu, mx, o));
    float e = __expf(q - mx);
    float s = e;
    #pragma unroll
    for (int o = 16; o > 0; o >>= 1)
        s += __shfl_xor_sync(0xffffffffu, s, o);
    float pr = __fdividef(e, s);
    // reference's extra /(sum+1e-10) is a no-op in f32 (sum==1)

    u64 pd = dup2(pr);
    #pragma unroll
    for (int j = 0; j < 8; ++j) acc2[j] = fma2(pd, V2[j], acc2[j]);
}

__global__ __launch_bounds__(256, 2)
void capsule_main(const float* __restrict__ input,
                  const float* __restrict__ ncv,
                  const float* __restrict__ wgt)
{
    extern __shared__ float smem[];
    float* s_inp = smem;                    // [16 n][3 k][31 col][16 ch]
    float* s_w   = smem + S_INP_FLOATS;     // [2][3*512] : 3 chunks of [x*4+dd][m]

    const int h    = blockIdx.x;
    const int b    = blockIdx.y;
    const int nh   = blockIdx.z;
    const int tid  = threadIdx.x;
    const int warp = tid >> 5;
    const int lane = tid & 31;               // m
    const int w0   = 2 * warp;
    const bool u1ok = (2 * warp + 1 < WOUT);
    const int w1   = u1ok ? 2 * warp + 1 : 14;   // warp 7: duplicate, store guarded
    const int n0   = nh * NHALF;

    // ---- input slice: rows 2h+k, cols 0..30, n0..n0+15 (coalesced float4) ----
    {
        const float4* gin = reinterpret_cast<const float4*>(input);
        float4* s4 = reinterpret_cast<float4*>(s_inp);
        #pragma unroll 1
        for (int i = tid; i < NHALF * 3 * 124; i += 256) {
            int nk = i / 124;
            int v  = i - nk * 124;
            int n  = nk / 3;
            int k  = nk - n * 3;
            s4[nk * 124 + v] = gin[(((b * 32 + n0 + n) * 32) + (2 * h + k)) * 128 + v];
        }
    }

    // ---- packed ncv for (b, m=lane, h, w0/w1) ----
    u64 ncv20[8], ncv21[8];
    {
        float t0[16], t1[16];
        ld16(t0, ncv + ((((size_t)b * 32 + lane) * HOUT + h) * WOUT + w0) * 16);
        ld16(t1, ncv + ((((size_t)b * 32 + lane) * HOUT + h) * WOUT + w1) * 16);
        #pragma unroll
        for (int j = 0; j < 8; ++j) {
            ncv20[j] = pack2(t0[2 * j], t0[2 * j + 1]);
            ncv21[j] = pack2(t1[2 * j], t1[2 * j + 1]);
        }
    }

    u64 acc20[8], acc21[8];
    #pragma unroll
    for (int j = 0; j < 8; ++j) { acc20[j] = 0ull; acc21[j] = 0ull; }

    const uint32_t swb = (uint32_t)__cvta_generic_to_shared(s_w);

    // preload w group (ni=0, kg=0): chunks kl=0..2, n=n0. chunk id = kl*32+n.
    #pragma unroll 1
    for (int i = tid; i < 384; i += 256) {
        int j = i >> 7, v = i & 127;
        cpasync16(swb + (uint32_t)(j * 512 + v * 4) * 4u,
                  (const float4*)(wgt + (size_t)(j * 32 + n0) * 512) + v);
    }
    asm volatile("cp.async.commit_group;");
    asm volatile("cp.async.wait_group 0;" ::: "memory");
    __syncthreads();

    int buf = 0;
    #pragma unroll 1
    for (int ni = 0; ni < NHALF; ++ni) {
        #pragma unroll 1
        for (int kg = 0; kg < 3; ++kg) {
            // prefetch next group
            {
                int ni2 = ni, kg2 = kg + 1;
                if (kg2 == 3) { kg2 = 0; ++ni2; }
                if (ni2 < NHALF) {
                    #pragma unroll 1
                    for (int i = tid; i < 384; i += 256) {
                        int j = i >> 7, v = i & 127;
                        const float4* src = (const float4*)(
                            wgt + (size_t)((kg2 * 3 + j) * 32 + n0 + ni2) * 512) + v;
                        cpasync16(swb + (uint32_t)((buf ^ 1) * 1536 + j * 512 + v * 4) * 4u,
                                  src);
                    }
                }
                asm volatile("cp.async.commit_group;");
            }

            const float* wgrp = s_w + buf * 1536;
            const float* rowbase = s_inp + (ni * 3 + kg) * 496;

            #pragma unroll
            for (int l = 0; l < 3; ++l) {
                const float* wb = wgrp + l * 512;
                // packed w pairs: wr2[x*2+p] = (w[x][2p], w[x][2p+1]) at m=lane
                u64 wr2[8];
                #pragma unroll
                for (int x = 0; x < 4; ++x) {
                    #pragma unroll
                    for (int p = 0; p < 2; ++p)
                        wr2[x * 2 + p] = pack2(wb[(x * 4 + 2 * p) * 32 + lane],
                                               wb[(x * 4 + 2 * p + 1) * 32 + lane]);
                }
                compute_unit(rowbase + (2 * w0 + l) * 16, wr2, ncv20, acc20);
                compute_unit(rowbase + (2 * w1 + l) * 16, wr2, ncv21, acc21);
            }

            asm volatile("cp.async.wait_group 0;" ::: "memory");
            __syncthreads();
            buf ^= 1;
        }
    }

    // ---- store raw partial sums (pre-LN) ----
    {
        float a0[16], a1[16];
        #pragma unroll
        for (int j = 0; j < 8; ++j) {
            unpack2(acc20[j], a0[2 * j], a0[2 * j + 1]);
            unpack2(acc21[j], a1[2 * j], a1[2 * j + 1]);
        }
        size_t site0 = (((size_t)b * 32 + lane) * HOUT + h) * WOUT + w0;
        float4* g0 = reinterpret_cast<float4*>(g_part + ((size_t)nh * NSITES + site0) * 16);
        g0[0] = make_float4(a0[0],  a0[1],  a0[2],  a0[3]);
        g0[1] = make_float4(a0[4],  a0[5],  a0[6],  a0[7]);
        g0[2] = make_float4(a0[8],  a0[9],  a0[10], a0[11]);
        g0[3] = make_float4(a0[12], a0[13], a0[14], a0[15]);
        if (u1ok) {
            float4* g1 = reinterpret_cast<float4*>(
                g_part + ((size_t)nh * NSITES + site0 + 1) * 16);
            g1[0] = make_float4(a1[0],  a1[1],  a1[2],  a1[3]);
            g1[1] = make_float4(a1[4],  a1[5],  a1[6],  a1[7]);
            g1[2] = make_float4(a1[8],  a1[9],  a1[10], a1[11]);
            g1[3] = make_float4(a1[12], a1[13], a1[14], a1[15]);
        }
    }
}

__global__ __launch_bounds__(256)
void reduce_ln(float* __restrict__ out,
               const float* __restrict__ gamma,
               const float* __restrict__ beta)
{
    int s = blockIdx.x * 256 + threadIdx.x;
    if (s >= NSITES) return;

    const float4* p0 = reinterpret_cast<const float4*>(g_part) + (size_t)s * 4;
    const float4* p1 = reinterpret_cast<const float4*>(g_part) + ((size_t)NSITES + s) * 4;

    float v[16];
    #pragma unroll
    for (int i = 0; i < 4; ++i) {
        float4 a = p0[i], c = p1[i];
        v[i * 4 + 0] = a.x + c.x;
        v[i * 4 + 1] = a.y + c.y;
        v[i * 4 + 2] = a.z + c.z;
        v[i * 4 + 3] = a.w + c.w;
    }

    float mu = 0.f;
    #pragma unroll
    for (int j = 0; j < 16; ++j) mu += v[j];
    mu *= (1.f / 16.f);
    float var = 0.f;
    #pragma unroll
    for (int j = 0; j < 16; ++j) { float d = v[j] - mu; var = fmaf(d, d, var); }
    var *= (1.f / 16.f);
    const float inv = rsqrtf(var + 1e-5f);

    float o[16];
    #pragma unroll
    for (int j = 0; j < 16; ++j)
        o[j] = fmaf((v[j] - mu) * inv, __ldg(gamma + j), __ldg(beta + j));

    float4* gout = reinterpret_cast<float4*>(out + (size_t)s * 16);
    gout[0] = make_float4(o[0],  o[1],  o[2],  o[3]);
    gout[1] = make_float4(o[4],  o[5],  o[6],  o[7]);
    gout[2] = make_float4(o[8],  o[9],  o[10], o[11]);
    gout[3] = make_float4(o[12], o[13], o[14], o[15]);
}

extern "C" void kernel_launch(void* const* d_in, const int* in_sizes, int n_in,
                              void* d_out, int out_size)
{
    const float* input = (const float*)d_in[0];
    const float* ncv   = (const float*)d_in[1];
    const float* wgt   = (const float*)d_in[2];
    const float* gamma = (const float*)d_in[3];
    const float* beta  = (const float*)d_in[4];
    float* out = (float*)d_out;

    cudaFuncSetAttribute(capsule_main,
                         cudaFuncAttributeMaxDynamicSharedMemorySize, SMEM_BYTES);
    dim3 grid(HOUT, 32, 2);
    capsule_main<<<grid, 256, SMEM_BYTES>>>(input, ncv, wgt);
    reduce_ln<<<(NSITES + 255) / 256, 256>>>(out, gamma, beta);
}